// round 5
// baseline (speedup 1.0000x reference)
#include <cuda_runtime.h>
#include <cstdint>

#define W      1280
#define H      720
#define BB     8
#define NROWS  (BB * H)        // 5760 rows
#define THREADS 64             // warp0: rgbm float4 RMW; warp1: occ scalar RMW
#define LANES  29              // active lanes per warp
#define CHUNKC 45              // per-lane chunk; C >= 41 + k  (k = sync interval)
#define STEPS  45
#define SYNCK  4
#define OFF    40              // x0 >= -40  ->  index x0+OFF >= 0
#define ACCW   1324            // 0..1320 real+right-pad, 1321 dummy, 1322 spill, pad
#define DUMMY  1321
#define EPSV   1e-6f
#define K_LOG2 0.49978215486f  // log2(1.414)

__global__ __launch_bounds__(THREADS, 4)
void warp_splat_kernel(const float* __restrict__ im,
                       const float* __restrict__ disp,
                       float* __restrict__ res,
                       float* __restrict__ occ) {
    __shared__ float  s_disp[W];
    __shared__ float  s_im[3][W];
    __shared__ float4 s_acc4[ACCW];   // (r, g, b, mask), index = x0 + OFF
    __shared__ float  s_occ[ACCW];

    const int row = blockIdx.x;            // 0..5759
    const int b = row / H;
    const int y = row - b * H;
    const float* drow  = disp + (size_t)row * W;
    const float* imrow = im + ((size_t)b * 3 * H + y) * W;

    const int t = threadIdx.x;

    // ---- stage inputs (coalesced float4) + zero accumulators ----
    {
        const float4* d4 = (const float4*)drow;
        float4* sd4 = (float4*)s_disp;
        for (int i = t; i < W / 4; i += THREADS) sd4[i] = d4[i];
        #pragma unroll
        for (int c = 0; c < 3; ++c) {
            const float4* i4 = (const float4*)(imrow + (size_t)c * H * W);
            float4* si4 = (float4*)s_im[c];
            for (int i = t; i < W / 4; i += THREADS) si4[i] = i4[i];
        }
        const float4 z4 = make_float4(0.f, 0.f, 0.f, 0.f);
        for (int i = t; i < ACCW; i += THREADS) s_acc4[i] = z4;
        float4* so4 = (float4*)s_occ;
        for (int i = t; i < ACCW / 4; i += THREADS) so4[i] = z4;
    }
    __syncthreads();

    const int lane = t & 31;
    const int warp = t >> 5;
    const int base = lane * CHUNKC;        // lanes 0..28 cover the row

    // Race-free drifting lockstep: at step s, lane l touches indices in
    // [45l+s-40, 45l+s+1]+OFF. With sync every 4 steps, reordering drift <= 3,
    // and C=45 >= 41+4 keeps adjacent-lane windows disjoint at all times.
    // Inactive/OOB lanes RMW a dedicated dummy slot (never a live one).
    if (warp == 0) {
        // (r, g, b, mask) accumulated as one float4 RMW per target
        #pragma unroll 1
        for (int blk = 0; blk < STEPS; blk += SYNCK) {
            #pragma unroll
            for (int u = 0; u < SYNCK; ++u) {
                const int s = blk + u;
                if (s < STEPS) {                       // warp-uniform branch
                    const int i  = base + s;
                    const int ic = min(i, W - 1);
                    const float d  = s_disp[ic];
                    const float x  = (float)i - d;
                    const int   x0 = __float2int_rd(x);
                    const float f  = x - (float)x0;
                    const bool act = (lane < LANES) && (i < W);
                    const int  xi  = act ? (x0 + OFF) : DUMMY;
                    float w;
                    asm("ex2.approx.f32 %0, %1;" : "=f"(w) : "f"(K_LOG2 * d));
                    const float wf = w * f;
                    const float w0 = w - wf;
                    const float r = s_im[0][ic];
                    const float g = s_im[1][ic];
                    const float bl = s_im[2][ic];
                    float4 lo = s_acc4[xi];
                    lo.x += r * w0;  lo.y += g * w0;
                    lo.z += bl * w0; lo.w += w0;
                    s_acc4[xi] = lo;
                    float4 hi = s_acc4[xi + 1];
                    hi.x += r * wf;  hi.y += g * wf;
                    hi.z += bl * wf; hi.w += wf;
                    s_acc4[xi + 1] = hi;
                }
            }
            __syncwarp();
        }
    } else {
        // occ: splat of ones (weights 1-f, f)
        #pragma unroll 1
        for (int blk = 0; blk < STEPS; blk += SYNCK) {
            #pragma unroll
            for (int u = 0; u < SYNCK; ++u) {
                const int s = blk + u;
                if (s < STEPS) {
                    const int i  = base + s;
                    const int ic = min(i, W - 1);
                    const float d  = s_disp[ic];
                    const float x  = (float)i - d;
                    const int   x0 = __float2int_rd(x);
                    const float f  = x - (float)x0;
                    const bool act = (lane < LANES) && (i < W);
                    const int  xi  = act ? (x0 + OFF) : DUMMY;
                    s_occ[xi]     += 1.0f - f;
                    s_occ[xi + 1] += f;
                }
            }
            __syncwarp();
        }
    }
    __syncthreads();

    // ---- writeback: res = acc/max(mask,eps), occ = 1 - clip(occacc,0,1) ----
    float* resrow = res + ((size_t)b * 3 * H + y) * W;
    float* occrow = occ + (size_t)row * W;
    for (int c = t; c < W; c += THREADS) {
        const float4 a = s_acc4[c + OFF];
        const float m = fmaxf(a.w, EPSV);
        float inv;
        asm("rcp.approx.f32 %0, %1;" : "=f"(inv) : "f"(m));
        resrow[c]                     = a.x * inv;
        resrow[(size_t)H * W + c]     = a.y * inv;
        resrow[(size_t)2 * H * W + c] = a.z * inv;
        const float o = s_occ[c + OFF];
        occrow[c] = 1.0f - fminf(fmaxf(o, 0.0f), 1.0f);
    }
}

extern "C" void kernel_launch(void* const* d_in, const int* in_sizes, int n_in,
                              void* d_out, int out_size) {
    const float* im   = (const float*)d_in[0];   // [8,3,720,1280]
    const float* disp = (const float*)d_in[1];   // [8,1,720,1280]
    float* res = (float*)d_out;                              // [8,3,720,1280]
    float* occ = (float*)d_out + (size_t)BB * 3 * H * W;     // [8,1,720,1280]

    // Note: reference subtracts global min(disp) in the exponent; that is a
    // common scale on w (1.414^dmin ~ 1+2e-6) which cancels in res = acc/mask
    // and doesn't affect occ -> skip the global reduction entirely.
    warp_splat_kernel<<<NROWS, THREADS>>>(im, disp, res, occ);
}

// round 7
// speedup vs baseline: 1.3018x; 1.3018x over previous
#include <cuda_runtime.h>
#include <cstdint>

#define W      1280
#define H      720
#define BB     8
#define NROWS  (BB * H)
#define THREADS 320            // 10 warps: (r,g,b,mask,occ) x (even,odd chunks)
#define CH     23              // chunk size; same-warp chunk stride = 46 >= 42+4
#define STEPS  23
#define SYNCK  4
#define ALANES 28              // active lanes per warp (56 chunks cover W=1280)
#define OFF    40
#define ACCW   1324            // indices 0..1320 live, 1321 dummy, pad to /4
#define DUMMY  1321
#define STG    1440            // padded staging: ix(i) = i + (i>>3), max 1438
#define EPSV   1e-6f
#define K_LOG2 0.49978215486f  // log2(1.414)

// shared layout (floats): stg_d[STG] | stg_im[3][STG] | acc[10][ACCW]
#define SM_D    0
#define SM_IM   (STG)
#define SM_ACC  (4 * STG)
#define SM_TOT  (4 * STG + 10 * ACCW)     // 19,000 floats = 76,000 B

__device__ __forceinline__ int ixpad(int i) { return i + (i >> 3); }

__global__ __launch_bounds__(THREADS, 3)
void warp_splat_kernel(const float* __restrict__ im,
                       const float* __restrict__ disp,
                       float* __restrict__ res,
                       float* __restrict__ occ) {
    extern __shared__ float sm[];

    const int row = blockIdx.x;
    const int b = row / H;
    const int y = row - b * H;
    const float* drow  = disp + (size_t)row * W;
    const float* imrow = im + ((size_t)b * 3 * H + y) * W;

    const int t = threadIdx.x;

    // ---- stage inputs into pad-mapped smem + zero accumulators ----
    for (int i = t; i < W; i += THREADS) {
        sm[SM_D + ixpad(i)] = drow[i];
        sm[SM_IM + 0 * STG + ixpad(i)] = imrow[i];
        sm[SM_IM + 1 * STG + ixpad(i)] = imrow[(size_t)H * W + i];
        sm[SM_IM + 2 * STG + ixpad(i)] = imrow[(size_t)2 * H * W + i];
    }
    {
        float4* a4 = (float4*)(sm + SM_ACC);
        const float4 z4 = make_float4(0.f, 0.f, 0.f, 0.f);
        for (int i = t; i < 10 * ACCW / 4; i += THREADS) a4[i] = z4;
    }
    __syncthreads();

    const int lane = t & 31;
    const int warp = t >> 5;          // 0..9
    const int arr  = warp >> 1;       // 0..4 : r,g,b,mask,occ
    const int par  = warp & 1;        // even/odd chunk parity
    // lane handles chunk q = 2*lane + par; base = q*CH = 46*lane + 23*par
    const int base = 46 * lane + CH * par;
    float* acc = sm + SM_ACC + warp * ACCW;
    const float* vsrc = sm + SM_IM + arr * STG;   // valid for arr<3

    // Race-free drifting lockstep within each warp: same-warp chunks are 46
    // apart; window width 42 + drift<=3 (SYNCK=4) keeps lanes disjoint.
    // Each warp owns a private acc copy -> no inter-warp races.
    #pragma unroll 1
    for (int blk = 0; blk < STEPS; blk += SYNCK) {
        #pragma unroll
        for (int u = 0; u < SYNCK; ++u) {
            const int s = blk + u;
            if (s < STEPS) {                      // warp-uniform
                const int i  = base + s;
                const int ic = min(i, W - 1);
                const float d  = sm[SM_D + ixpad(ic)];
                const float x  = (float)i - d;
                const int   x0 = __float2int_rd(x);
                const float f  = x - (float)x0;
                const bool act = (lane < ALANES) && (i < W);
                const int  xi  = act ? (x0 + OFF) : DUMMY;
                float a0, a1;
                if (arr == 4) {                   // occ: splat of ones
                    a0 = 1.0f - f; a1 = f;
                } else {
                    float w;
                    asm("ex2.approx.f32 %0, %1;" : "=f"(w) : "f"(K_LOG2 * d));
                    const float wf = w * f;
                    const float w0 = w - wf;
                    if (arr == 3) { a0 = w0; a1 = wf; }          // mask
                    else {
                        const float v = vsrc[ixpad(ic)];         // r/g/b
                        a0 = v * w0; a1 = v * wf;
                    }
                }
                acc[xi]     += a0;
                acc[xi + 1] += a1;
            }
        }
        __syncwarp();
    }
    __syncthreads();

    // ---- writeback: sum parity copies; res = acc/max(mask,eps), occ = 1-clip ----
    float* resrow = res + ((size_t)b * 3 * H + y) * W;
    float* occrow = occ + (size_t)row * W;
    const float* A = sm + SM_ACC;
    for (int c = t; c < W; c += THREADS) {
        const int k = c + OFF;
        const float rv = A[0 * ACCW + k] + A[1 * ACCW + k];
        const float gv = A[2 * ACCW + k] + A[3 * ACCW + k];
        const float bv = A[4 * ACCW + k] + A[5 * ACCW + k];
        const float mv = A[6 * ACCW + k] + A[7 * ACCW + k];
        const float ov = A[8 * ACCW + k] + A[9 * ACCW + k];
        const float m = fmaxf(mv, EPSV);
        float inv;
        asm("rcp.approx.f32 %0, %1;" : "=f"(inv) : "f"(m));
        resrow[c]                     = rv * inv;
        resrow[(size_t)H * W + c]     = gv * inv;
        resrow[(size_t)2 * H * W + c] = bv * inv;
        occrow[c] = 1.0f - fminf(fmaxf(ov, 0.0f), 1.0f);
    }
}

extern "C" void kernel_launch(void* const* d_in, const int* in_sizes, int n_in,
                              void* d_out, int out_size) {
    const float* im   = (const float*)d_in[0];   // [8,3,720,1280]
    const float* disp = (const float*)d_in[1];   // [8,1,720,1280]
    float* res = (float*)d_out;                              // [8,3,720,1280]
    float* occ = (float*)d_out + (size_t)BB * 3 * H * W;     // [8,1,720,1280]

    // Unconditional (no static guard): deterministic, idempotent attribute set;
    // enqueues no stream work, so it is graph-capture-safe.
    cudaFuncSetAttribute(warp_splat_kernel,
                         cudaFuncAttributeMaxDynamicSharedMemorySize,
                         SM_TOT * sizeof(float));
    // dmin elision: 1.414^dmin is a common scale on w (~1+2e-6) that cancels
    // in res = acc/mask and doesn't enter occ -> skip the global reduction.
    warp_splat_kernel<<<NROWS, THREADS, SM_TOT * sizeof(float)>>>(im, disp, res, occ);
}